// round 1
// baseline (speedup 1.0000x reference)
#include <cuda_runtime.h>
#include <cuda_bf16.h>
#include <math.h>

// Problem constants (fixed by the reference)
#define Hdim 1024
#define Idim 2048
#define Edim 8
#define Ntok 8192            // B*T = 4*2048
#define KSEL 2
#define NSLOT (Ntok * KSEL)  // 16384

// ---------------- device scratch (allocation-free rule: __device__ globals) ---
__device__ float g_xg [(size_t)NSLOT * Hdim];   // gathered activations, per-expert contiguous
__device__ float g_hid[(size_t)NSLOT * Idim];   // fc1 output after silu
__device__ float g_og [(size_t)NSLOT * Hdim];   // fc2 output per (token,slot)
__device__ int   g_counts[Edim];
__device__ int   g_off[Edim];
__device__ int   g_expert[NSLOT];
__device__ int   g_rank[NSLOT];
__device__ float g_w[NSLOT];
__device__ int   g_pos[NSLOT];

// ---------------- kernels ----------------------------------------------------

__global__ void zero_counts_kernel() {
    if (threadIdx.x < Edim) g_counts[threadIdx.x] = 0;
}

// One block per token; warp e computes logit for expert e; thread 0 does
// softmax + top-2 + rank assignment.
__global__ __launch_bounds__(256) void gate_kernel(const float* __restrict__ x,
                                                   const float* __restrict__ Wg) {
    int n    = blockIdx.x;
    int warp = threadIdx.x >> 5;
    int lane = threadIdx.x & 31;

    const float* xr = x  + (size_t)n * Hdim;
    const float* wr = Wg + (size_t)warp * Hdim;
    float s = 0.f;
    #pragma unroll 8
    for (int h = lane; h < Hdim; h += 32) s += xr[h] * wr[h];
    #pragma unroll
    for (int o = 16; o; o >>= 1) s += __shfl_xor_sync(0xFFFFFFFFu, s, o);

    __shared__ float logits[Edim];
    if (lane == 0) logits[warp] = s;
    __syncthreads();

    if (threadIdx.x == 0) {
        float m = logits[0];
        #pragma unroll
        for (int e = 1; e < Edim; e++) m = fmaxf(m, logits[e]);
        float p[Edim]; float den = 0.f;
        #pragma unroll
        for (int e = 0; e < Edim; e++) { p[e] = expf(logits[e] - m); den += p[e]; }

        // top-2 (strict > keeps lowest index on ties, matching jax.lax.top_k)
        int i0 = 0;
        #pragma unroll
        for (int e = 1; e < Edim; e++) if (p[e] > p[i0]) i0 = e;
        int i1 = (i0 == 0) ? 1 : 0;
        #pragma unroll
        for (int e = 0; e < Edim; e++) if (e != i0 && p[e] > p[i1]) i1 = e;

        float inv = 1.f / den;
        int r0 = atomicAdd(&g_counts[i0], 1);
        int r1 = atomicAdd(&g_counts[i1], 1);
        int s0 = 2 * n, s1 = 2 * n + 1;
        g_expert[s0] = i0; g_rank[s0] = r0; g_w[s0] = p[i0] * inv;
        g_expert[s1] = i1; g_rank[s1] = r1; g_w[s1] = p[i1] * inv;
    }
}

__global__ void scan_kernel() {
    if (threadIdx.x == 0) {
        int a = 0;
        #pragma unroll
        for (int e = 0; e < Edim; e++) { g_off[e] = a; a += g_counts[e]; }
    }
}

// One block per (token,slot): copy the token row into its expert-group position.
__global__ __launch_bounds__(256) void gather_kernel(const float* __restrict__ x) {
    int slot = blockIdx.x;
    int e    = g_expert[slot];
    int pos  = g_off[e] + g_rank[slot];
    if (threadIdx.x == 0) g_pos[slot] = pos;
    int n = slot >> 1;
    const float4* src = (const float4*)(x + (size_t)n * Hdim);
    float4*       dst = (float4*)(g_xg + (size_t)pos * Hdim);
    for (int i = threadIdx.x; i < Hdim / 4; i += blockDim.x) dst[i] = src[i];
}

// Grouped NT GEMM: C[m,nc] = sum_k A[m,k] * W[e][nc,k]; optional fused SiLU.
// A rows for expert e are contiguous starting at g_off[e]; Me = g_counts[e].
#define BM 64
#define BN 64
#define BKT 16
__global__ __launch_bounds__(256) void moe_gemm_kernel(
    const float* __restrict__ Abase, const float* __restrict__ Wbase,
    float* __restrict__ Cbase, int Kdim, int Ncols, int do_silu)
{
    int e  = blockIdx.z;
    int Me = g_counts[e];
    int m0 = blockIdx.y * BM;
    if (m0 >= Me) return;
    int n0 = blockIdx.x * BN;

    const float* A  = Abase + (size_t)g_off[e] * Kdim;
    const float* Bw = Wbase + (size_t)e * Ncols * Kdim;
    float*       C  = Cbase + (size_t)g_off[e] * Ncols;

    __shared__ float As[BKT][BM + 4];
    __shared__ float Bs[BKT][BN + 4];

    int tid = threadIdx.x;
    int tx = tid & 15, ty = tid >> 4;
    int lr = tid >> 2;         // load row within tile 0..63
    int lk = (tid & 3) * 4;    // k sub-offset 0,4,8,12

    float acc[4][4] = {};

    for (int k0 = 0; k0 < Kdim; k0 += BKT) {
        float4 av;
        if (m0 + lr < Me)
            av = *(const float4*)(A + (size_t)(m0 + lr) * Kdim + k0 + lk);
        else
            av = make_float4(0.f, 0.f, 0.f, 0.f);
        As[lk + 0][lr] = av.x; As[lk + 1][lr] = av.y;
        As[lk + 2][lr] = av.z; As[lk + 3][lr] = av.w;

        float4 bv = *(const float4*)(Bw + (size_t)(n0 + lr) * Kdim + k0 + lk);
        Bs[lk + 0][lr] = bv.x; Bs[lk + 1][lr] = bv.y;
        Bs[lk + 2][lr] = bv.z; Bs[lk + 3][lr] = bv.w;
        __syncthreads();

        #pragma unroll
        for (int kk = 0; kk < BKT; kk++) {
            float4 a = *(const float4*)&As[kk][ty * 4];
            float4 b = *(const float4*)&Bs[kk][tx * 4];
            float ar[4] = {a.x, a.y, a.z, a.w};
            float br[4] = {b.x, b.y, b.z, b.w};
            #pragma unroll
            for (int i = 0; i < 4; i++)
                #pragma unroll
                for (int j = 0; j < 4; j++)
                    acc[i][j] = fmaf(ar[i], br[j], acc[i][j]);
        }
        __syncthreads();
    }

    #pragma unroll
    for (int i = 0; i < 4; i++) {
        int m = m0 + ty * 4 + i;
        if (m >= Me) break;
        #pragma unroll
        for (int j = 0; j < 4; j++) {
            float v = acc[i][j];
            if (do_silu) v = v / (1.f + expf(-v));
            C[(size_t)m * Ncols + n0 + tx * 4 + j] = v;
        }
    }
}

__global__ __launch_bounds__(256) void combine_kernel(float* __restrict__ out) {
    int idx = blockIdx.x * blockDim.x + threadIdx.x;   // over N*H/4
    int n = idx / (Hdim / 4);
    int c = idx % (Hdim / 4);
    float w0 = g_w[2 * n],   w1 = g_w[2 * n + 1];
    int   p0 = g_pos[2 * n], p1 = g_pos[2 * n + 1];
    float4 a = ((const float4*)(g_og + (size_t)p0 * Hdim))[c];
    float4 b = ((const float4*)(g_og + (size_t)p1 * Hdim))[c];
    float4 r;
    r.x = w0 * a.x + w1 * b.x;
    r.y = w0 * a.y + w1 * b.y;
    r.z = w0 * a.z + w1 * b.z;
    r.w = w0 * a.w + w1 * b.w;
    ((float4*)out)[idx] = r;
}

// ---------------- launch ------------------------------------------------------
extern "C" void kernel_launch(void* const* d_in, const int* in_sizes, int n_in,
                              void* d_out, int out_size) {
    const float* x  = (const float*)d_in[0];
    const float* Wg = (const float*)d_in[1];
    const float* W1 = (const float*)d_in[2];
    const float* W2 = (const float*)d_in[3];
    float* out = (float*)d_out;

    float* xg  = nullptr; float* hid = nullptr; float* og = nullptr;
    cudaGetSymbolAddress((void**)&xg,  g_xg);
    cudaGetSymbolAddress((void**)&hid, g_hid);
    cudaGetSymbolAddress((void**)&og,  g_og);

    zero_counts_kernel<<<1, 32>>>();
    gate_kernel<<<Ntok, 256>>>(x, Wg);
    scan_kernel<<<1, 32>>>();
    gather_kernel<<<NSLOT, 256>>>(x);

    // GEMM1: hid = silu(xg @ W1[e]^T)   K=H=1024, Ncols=I=2048
    {
        dim3 grid(Idim / BN, (Ntok + BM - 1) / BM, Edim);
        moe_gemm_kernel<<<grid, 256>>>(xg, W1, hid, Hdim, Idim, 1);
    }
    // GEMM2: og = hid @ W2[e]^T         K=I=2048, Ncols=H=1024
    {
        dim3 grid(Hdim / BN, (Ntok + BM - 1) / BM, Edim);
        moe_gemm_kernel<<<grid, 256>>>(hid, W2, og, Idim, Hdim, 0);
    }
    combine_kernel<<<(Ntok * Hdim / 4) / 256, 256>>>(out);
}

// round 3
// speedup vs baseline: 2.2263x; 2.2263x over previous
#include <cuda_runtime.h>
#include <cuda_bf16.h>
#include <math.h>
#include <stdint.h>

// Problem constants (fixed by the reference)
#define Hdim 1024
#define Idim 2048
#define Edim 8
#define Ntok 8192            // B*T
#define KSEL 2
#define NSLOT (Ntok * KSEL)  // 16384

// ---------------- device scratch ---------------------------------------------
__device__ float g_xg [(size_t)NSLOT * Hdim];   // gathered activations (tf32-RNE-prepped)
__device__ float g_hid[(size_t)NSLOT * Idim];   // fc1 out (silu, prepped)
__device__ float g_og [(size_t)NSLOT * Hdim];   // fc2 out
__device__ int   g_counts[Edim];
__device__ int   g_off[Edim];
__device__ int   g_expert[NSLOT];
__device__ int   g_rank[NSLOT];
__device__ float g_w[NSLOT];
__device__ int   g_pos[NSLOT];

// ---------------- helpers -----------------------------------------------------
__device__ __forceinline__ float tf32_rne_prep(float v) {
    // Add rounding increment so HW truncation to tf32 (drop low 13 bits) = RNE.
    uint32_t b = __float_as_uint(v);
    b += 0xFFFu + ((b >> 13) & 1u);
    return __uint_as_float(b);
}

__device__ __forceinline__ uint32_t smem_u32(const void* p) {
    uint32_t a;
    asm("{ .reg .u64 t; cvta.to.shared.u64 t, %1; cvt.u32.u64 %0, t; }" : "=r"(a) : "l"(p));
    return a;
}

__device__ __forceinline__ void cp16(uint32_t dst, const float* src) {
    asm volatile("cp.async.cg.shared.global [%0], [%1], 16;" :: "r"(dst), "l"(src));
}

__device__ __forceinline__ void ldsm_x4(uint32_t addr, uint32_t& r0, uint32_t& r1,
                                        uint32_t& r2, uint32_t& r3) {
    asm volatile("ldmatrix.sync.aligned.m8n8.x4.shared.b16 {%0,%1,%2,%3}, [%4];"
                 : "=r"(r0), "=r"(r1), "=r"(r2), "=r"(r3) : "r"(addr));
}

__device__ __forceinline__ uint32_t cvt_tf32(uint32_t bits) {
    uint32_t o;
    asm("cvt.rna.tf32.f32 %0, %1;" : "=r"(o) : "f"(__uint_as_float(bits)));
    return o;
}

__device__ __forceinline__ void mma_tf32(float* d, const uint32_t* a, uint32_t b0, uint32_t b1) {
    asm volatile(
        "mma.sync.aligned.m16n8k8.row.col.f32.tf32.tf32.f32 "
        "{%0,%1,%2,%3}, {%4,%5,%6,%7}, {%8,%9}, {%0,%1,%2,%3};"
        : "+f"(d[0]), "+f"(d[1]), "+f"(d[2]), "+f"(d[3])
        : "r"(a[0]), "r"(a[1]), "r"(a[2]), "r"(a[3]), "r"(b0), "r"(b1));
}

// ---------------- ancillary kernels ------------------------------------------
__global__ void zero_counts_kernel() {
    if (threadIdx.x < Edim) g_counts[threadIdx.x] = 0;
}

__global__ __launch_bounds__(256) void gate_kernel(const float* __restrict__ x,
                                                   const float* __restrict__ Wg) {
    int n    = blockIdx.x;
    int warp = threadIdx.x >> 5;
    int lane = threadIdx.x & 31;

    const float* xr = x  + (size_t)n * Hdim;
    const float* wr = Wg + (size_t)warp * Hdim;
    float s = 0.f;
    #pragma unroll 8
    for (int h = lane; h < Hdim; h += 32) s += xr[h] * wr[h];
    #pragma unroll
    for (int o = 16; o; o >>= 1) s += __shfl_xor_sync(0xFFFFFFFFu, s, o);

    __shared__ float logits[Edim];
    if (lane == 0) logits[warp] = s;
    __syncthreads();

    if (threadIdx.x == 0) {
        float m = logits[0];
        #pragma unroll
        for (int e = 1; e < Edim; e++) m = fmaxf(m, logits[e]);
        float p[Edim]; float den = 0.f;
        #pragma unroll
        for (int e = 0; e < Edim; e++) { p[e] = expf(logits[e] - m); den += p[e]; }
        int i0 = 0;
        #pragma unroll
        for (int e = 1; e < Edim; e++) if (p[e] > p[i0]) i0 = e;
        int i1 = (i0 == 0) ? 1 : 0;
        #pragma unroll
        for (int e = 0; e < Edim; e++) if (e != i0 && p[e] > p[i1]) i1 = e;
        float inv = 1.f / den;
        int r0 = atomicAdd(&g_counts[i0], 1);
        int r1 = atomicAdd(&g_counts[i1], 1);
        g_expert[2*n]   = i0; g_rank[2*n]   = r0; g_w[2*n]   = p[i0] * inv;
        g_expert[2*n+1] = i1; g_rank[2*n+1] = r1; g_w[2*n+1] = p[i1] * inv;
    }
}

__global__ void scan_kernel() {
    if (threadIdx.x == 0) {
        int a = 0;
        #pragma unroll
        for (int e = 0; e < Edim; e++) { g_off[e] = a; a += g_counts[e]; }
    }
}

__global__ __launch_bounds__(256) void gather_kernel(const float* __restrict__ x) {
    int slot = blockIdx.x;
    int e    = g_expert[slot];
    int pos  = g_off[e] + g_rank[slot];
    if (threadIdx.x == 0) g_pos[slot] = pos;
    int n = slot >> 1;
    const float4* src = (const float4*)(x + (size_t)n * Hdim);
    float4*       dst = (float4*)(g_xg + (size_t)pos * Hdim);
    for (int i = threadIdx.x; i < Hdim / 4; i += blockDim.x) {
        float4 v = src[i];
        v.x = tf32_rne_prep(v.x); v.y = tf32_rne_prep(v.y);
        v.z = tf32_rne_prep(v.z); v.w = tf32_rne_prep(v.w);
        dst[i] = v;
    }
}

__global__ __launch_bounds__(256) void combine_kernel(float* __restrict__ out) {
    int idx = blockIdx.x * blockDim.x + threadIdx.x;   // over N*H/4
    int n = idx / (Hdim / 4);
    int c = idx % (Hdim / 4);
    float w0 = g_w[2*n],   w1 = g_w[2*n+1];
    int   p0 = g_pos[2*n], p1 = g_pos[2*n+1];
    float4 a = ((const float4*)(g_og + (size_t)p0 * Hdim))[c];
    float4 b = ((const float4*)(g_og + (size_t)p1 * Hdim))[c];
    float4 r;
    r.x = w0 * a.x + w1 * b.x;
    r.y = w0 * a.y + w1 * b.y;
    r.z = w0 * a.z + w1 * b.z;
    r.w = w0 * a.w + w1 * b.w;
    ((float4*)out)[idx] = r;
}

// ---------------- tf32 mma.sync grouped GEMM ---------------------------------
// C[m,nc] = sum_k A[m,k] * W[e][nc,k]  (both K-contiguous; "row.col" MMA).
// CTA tile 128x128x32; 8 warps, warp tile 64x32 (4x4 m16n8k8). 4-stage cp.async.
#define STAGE_BYTES 32768           // A 16KB + B 16KB
#define NSTAGE 4
#define SMEM_TOTAL (NSTAGE * STAGE_BYTES)

__global__ __launch_bounds__(256) void moe_gemm_mma(
    const float* __restrict__ Ab, const float* __restrict__ Wb,
    float* __restrict__ Cb, int Kdim, int Ncols, int do_silu)
{
    int e  = blockIdx.z;
    int Me = g_counts[e];
    int m0 = blockIdx.y * 128;
    if (m0 >= Me) return;
    int n0  = blockIdx.x * 128;
    int off = g_off[e];

    extern __shared__ char smem[];
    uint32_t sb = smem_u32(smem);
    int tid = threadIdx.x, wid = tid >> 5, lane = tid & 31;

    const float* A = Ab + (size_t)off * Kdim;
    const float* W = Wb + (size_t)e * Ncols * Kdim;
    float*       C = Cb + (size_t)off * Ncols;

    // ---- staging role: threads 0-127 load A rows, 128-255 load B rows -------
    int  srow = tid & 127;
    bool isB  = tid >= 128;
    const float* gsrc = isB ? (W + (size_t)(n0 + srow) * Kdim)
                            : (A + (size_t)min(m0 + srow, NSLOT - 1 - off) * Kdim);
    uint32_t sdst = sb + (isB ? 16384u : 0u) + (uint32_t)srow * 128u;
    uint32_t sx   = (uint32_t)(srow & 7);

    // ---- ldmatrix address bases ---------------------------------------------
    int mw = wid & 1, nw = wid >> 1;           // warp grid 2(m) x 4(n)
    int mA0 = mw * 64, nB0 = nw * 32;

    // A: matrices q=lane>>3: row sel (q&1)*8, k-half sel q>>1
    int rA = mA0 + ((lane >> 3) & 1) * 8 + (lane & 7);
    uint32_t jhA = (uint32_t)(lane >> 4);
    uint32_t xA  = (uint32_t)(rA & 7);
    uint32_t baseA[4];
    #pragma unroll
    for (int mt = 0; mt < 4; mt++) baseA[mt] = sb + (uint32_t)(rA + mt * 16) * 128u;

    // B: pair p covers ntiles 2p,2p+1: q&1 = k-half, q>>1 = +8 n-rows
    uint32_t jhB = (uint32_t)((lane >> 3) & 1);
    uint32_t baseB[2], xB[2];
    #pragma unroll
    for (int p = 0; p < 2; p++) {
        int rB = nB0 + p * 16 + (lane >> 4) * 8 + (lane & 7);
        baseB[p] = sb + 16384u + (uint32_t)rB * 128u;
        xB[p]    = (uint32_t)(rB & 7);
    }

    float acc[4][4][4];
    #pragma unroll
    for (int i = 0; i < 4; i++)
        #pragma unroll
        for (int j = 0; j < 4; j++)
            #pragma unroll
            for (int q = 0; q < 4; q++) acc[i][j][q] = 0.f;

    int niter = Kdim >> 5;

    // ---- prologue: stages 0..2 ----------------------------------------------
    #pragma unroll
    for (int s = 0; s < NSTAGE - 1; s++) {
        uint32_t d = sdst + (uint32_t)s * STAGE_BYTES;
        const float* g = gsrc + s * 32;
        #pragma unroll
        for (int j = 0; j < 8; j++) cp16(d + (((uint32_t)j ^ sx) << 4), g + j * 4);
        asm volatile("cp.async.commit_group;");
    }

    for (int it = 0; it < niter; ++it) {
        asm volatile("cp.async.wait_group 2;");
        __syncthreads();

        uint32_t soff = (uint32_t)(it & (NSTAGE - 1)) * STAGE_BYTES;

        #pragma unroll
        for (int ks = 0; ks < 4; ks++) {
            uint32_t a[4][4];
            #pragma unroll
            for (int mt = 0; mt < 4; mt++) {
                uint32_t ad = baseA[mt] + soff + ((((uint32_t)(ks << 1) + jhA) ^ xA) << 4);
                ldsm_x4(ad, a[mt][0], a[mt][1], a[mt][2], a[mt][3]);
            }
            #pragma unroll
            for (int p = 0; p < 2; p++) {
                uint32_t b0, b1, b2, b3;
                uint32_t bd = baseB[p] + soff + ((((uint32_t)(ks << 1) + jhB) ^ xB[p]) << 4);
                ldsm_x4(bd, b0, b1, b2, b3);
                b0 = cvt_tf32(b0); b1 = cvt_tf32(b1);
                b2 = cvt_tf32(b2); b3 = cvt_tf32(b3);
                #pragma unroll
                for (int mt = 0; mt < 4; mt++) {
                    mma_tf32(acc[mt][2 * p + 0], a[mt], b0, b1);
                    mma_tf32(acc[mt][2 * p + 1], a[mt], b2, b3);
                }
            }
        }

        int nx = it + NSTAGE - 1;
        if (nx < niter) {
            uint32_t d = sdst + (uint32_t)(nx & (NSTAGE - 1)) * STAGE_BYTES;
            const float* g = gsrc + nx * 32;
            #pragma unroll
            for (int j = 0; j < 8; j++) cp16(d + (((uint32_t)j ^ sx) << 4), g + j * 4);
        }
        asm volatile("cp.async.commit_group;");
    }

    // ---- epilogue ------------------------------------------------------------
    #pragma unroll
    for (int mt = 0; mt < 4; mt++) {
        int ml0 = mA0 + mt * 16 + (lane >> 2);
        int ml1 = ml0 + 8;
        bool w0 = (m0 + ml0) < Me;
        bool w1 = (m0 + ml1) < Me;
        float* c0 = C + (size_t)(m0 + ml0) * Ncols + n0;
        float* c1 = C + (size_t)(m0 + ml1) * Ncols + n0;
        #pragma unroll
        for (int nt = 0; nt < 4; nt++) {
            int col = nB0 + nt * 8 + (lane & 3) * 2;
            float v0 = acc[mt][nt][0], v1 = acc[mt][nt][1];
            float v2 = acc[mt][nt][2], v3 = acc[mt][nt][3];
            if (do_silu) {
                v0 = tf32_rne_prep(v0 / (1.f + __expf(-v0)));
                v1 = tf32_rne_prep(v1 / (1.f + __expf(-v1)));
                v2 = tf32_rne_prep(v2 / (1.f + __expf(-v2)));
                v3 = tf32_rne_prep(v3 / (1.f + __expf(-v3)));
            }
            if (w0) *(float2*)(c0 + col) = make_float2(v0, v1);
            if (w1) *(float2*)(c1 + col) = make_float2(v2, v3);
        }
    }
}

// ---------------- launch ------------------------------------------------------
extern "C" void kernel_launch(void* const* d_in, const int* in_sizes, int n_in,
                              void* d_out, int out_size) {
    const float* x  = (const float*)d_in[0];
    const float* Wg = (const float*)d_in[1];
    const float* W1 = (const float*)d_in[2];
    const float* W2 = (const float*)d_in[3];
    float* out = (float*)d_out;

    float *xg = nullptr, *hid = nullptr, *og = nullptr;
    cudaGetSymbolAddress((void**)&xg,  g_xg);
    cudaGetSymbolAddress((void**)&hid, g_hid);
    cudaGetSymbolAddress((void**)&og,  g_og);

    static bool attr_set = false;
    if (!attr_set) {
        cudaFuncSetAttribute(moe_gemm_mma, cudaFuncAttributeMaxDynamicSharedMemorySize,
                             SMEM_TOTAL);
        attr_set = true;
    }

    zero_counts_kernel<<<1, 32>>>();
    gate_kernel<<<Ntok, 256>>>(x, Wg);
    scan_kernel<<<1, 32>>>();
    gather_kernel<<<NSLOT, 256>>>(x);

    // GEMM1: hid = silu(xg @ W1[e]^T)   K=H=1024, Ncols=I=2048
    {
        dim3 grid(Idim / 128, NSLOT / 128, Edim);
        moe_gemm_mma<<<grid, 256, SMEM_TOTAL>>>(xg, W1, hid, Hdim, Idim, 1);
    }
    // GEMM2: og = hid @ W2[e]^T         K=I=2048, Ncols=H=1024
    {
        dim3 grid(Hdim / 128, NSLOT / 128, Edim);
        moe_gemm_mma<<<grid, 256, SMEM_TOTAL>>>(hid, W2, og, Idim, Hdim, 0);
    }
    combine_kernel<<<(Ntok * Hdim / 4) / 256, 256>>>(out);
}

// round 4
// speedup vs baseline: 3.7742x; 1.6953x over previous
#include <cuda_runtime.h>
#include <cuda_fp16.h>
#include <math.h>
#include <stdint.h>

// Problem constants (fixed by the reference)
#define Hdim 1024
#define Idim 2048
#define Edim 8
#define Ntok 8192            // B*T
#define KSEL 2
#define NSLOT (Ntok * KSEL)  // 16384
#define W1ELEMS (Edim * Idim * Hdim)
#define W2ELEMS (Edim * Hdim * Idim)

// ---------------- device scratch ---------------------------------------------
__device__ __half g_xh  [(size_t)NSLOT * Hdim];  // gathered activations (fp16)
__device__ __half g_hidh[(size_t)NSLOT * Idim];  // fc1 out after silu (fp16)
__device__ float  g_og  [(size_t)NSLOT * Hdim];  // fc2 out (fp32)
__device__ __half g_w1h [W1ELEMS];
__device__ __half g_w2h [W2ELEMS];
__device__ int    g_counts[Edim];
__device__ int    g_off[Edim];
__device__ int    g_expert[NSLOT];
__device__ int    g_rank[NSLOT];
__device__ float  g_w[NSLOT];
__device__ int    g_pos[NSLOT];

// ---------------- helpers -----------------------------------------------------
__device__ __forceinline__ uint32_t smem_u32(const void* p) {
    uint32_t a;
    asm("{ .reg .u64 t; cvta.to.shared.u64 t, %1; cvt.u32.u64 %0, t; }" : "=r"(a) : "l"(p));
    return a;
}

__device__ __forceinline__ void cp16(uint32_t dst, const void* src) {
    asm volatile("cp.async.cg.shared.global [%0], [%1], 16;" :: "r"(dst), "l"(src));
}

__device__ __forceinline__ void ldsm_x4(uint32_t addr, uint32_t& r0, uint32_t& r1,
                                        uint32_t& r2, uint32_t& r3) {
    asm volatile("ldmatrix.sync.aligned.m8n8.x4.shared.b16 {%0,%1,%2,%3}, [%4];"
                 : "=r"(r0), "=r"(r1), "=r"(r2), "=r"(r3) : "r"(addr));
}

__device__ __forceinline__ void mma_f16(float* d, const uint32_t* a, uint32_t b0, uint32_t b1) {
    asm volatile(
        "mma.sync.aligned.m16n8k16.row.col.f32.f16.f16.f32 "
        "{%0,%1,%2,%3}, {%4,%5,%6,%7}, {%8,%9}, {%0,%1,%2,%3};"
        : "+f"(d[0]), "+f"(d[1]), "+f"(d[2]), "+f"(d[3])
        : "r"(a[0]), "r"(a[1]), "r"(a[2]), "r"(a[3]), "r"(b0), "r"(b1));
}

// ---------------- ancillary kernels ------------------------------------------
__global__ void zero_counts_kernel() {
    if (threadIdx.x < Edim) g_counts[threadIdx.x] = 0;
}

__global__ __launch_bounds__(256) void gate_kernel(const float* __restrict__ x,
                                                   const float* __restrict__ Wg) {
    int n    = blockIdx.x;
    int warp = threadIdx.x >> 5;
    int lane = threadIdx.x & 31;

    const float* xr = x  + (size_t)n * Hdim;
    const float* wr = Wg + (size_t)warp * Hdim;
    float s = 0.f;
    #pragma unroll 8
    for (int h = lane; h < Hdim; h += 32) s += xr[h] * wr[h];
    #pragma unroll
    for (int o = 16; o; o >>= 1) s += __shfl_xor_sync(0xFFFFFFFFu, s, o);

    __shared__ float logits[Edim];
    if (lane == 0) logits[warp] = s;
    __syncthreads();

    if (threadIdx.x == 0) {
        float m = logits[0];
        #pragma unroll
        for (int e = 1; e < Edim; e++) m = fmaxf(m, logits[e]);
        float p[Edim]; float den = 0.f;
        #pragma unroll
        for (int e = 0; e < Edim; e++) { p[e] = expf(logits[e] - m); den += p[e]; }
        int i0 = 0;
        #pragma unroll
        for (int e = 1; e < Edim; e++) if (p[e] > p[i0]) i0 = e;
        int i1 = (i0 == 0) ? 1 : 0;
        #pragma unroll
        for (int e = 0; e < Edim; e++) if (e != i0 && p[e] > p[i1]) i1 = e;
        float inv = 1.f / den;
        int r0 = atomicAdd(&g_counts[i0], 1);
        int r1 = atomicAdd(&g_counts[i1], 1);
        g_expert[2*n]   = i0; g_rank[2*n]   = r0; g_w[2*n]   = p[i0] * inv;
        g_expert[2*n+1] = i1; g_rank[2*n+1] = r1; g_w[2*n+1] = p[i1] * inv;
    }
}

__global__ void scan_kernel() {
    if (threadIdx.x == 0) {
        int a = 0;
        #pragma unroll
        for (int e = 0; e < Edim; e++) { g_off[e] = a; a += g_counts[e]; }
    }
}

__global__ __launch_bounds__(256) void gather_kernel(const float* __restrict__ x) {
    int slot = blockIdx.x;
    int e    = g_expert[slot];
    int pos  = g_off[e] + g_rank[slot];
    if (threadIdx.x == 0) g_pos[slot] = pos;
    int n = slot >> 1;
    const float4* src = (const float4*)(x + (size_t)n * Hdim);
    __half2*      dst = (__half2*)(g_xh + (size_t)pos * Hdim);
    for (int i = threadIdx.x; i < Hdim / 4; i += blockDim.x) {
        float4 v = src[i];
        dst[2*i]   = __floats2half2_rn(v.x, v.y);
        dst[2*i+1] = __floats2half2_rn(v.z, v.w);
    }
}

// float -> half weight conversion, 8 elems per thread
__global__ __launch_bounds__(256) void f2h_kernel(const float* __restrict__ s,
                                                  __half* __restrict__ d, int n8) {
    int i = blockIdx.x * blockDim.x + threadIdx.x;
    if (i >= n8) return;
    float4 v0 = ((const float4*)s)[2*i];
    float4 v1 = ((const float4*)s)[2*i+1];
    __half2 h[4];
    h[0] = __floats2half2_rn(v0.x, v0.y);
    h[1] = __floats2half2_rn(v0.z, v0.w);
    h[2] = __floats2half2_rn(v1.x, v1.y);
    h[3] = __floats2half2_rn(v1.z, v1.w);
    ((uint4*)d)[i] = *(uint4*)h;
}

__global__ __launch_bounds__(256) void combine_kernel(float* __restrict__ out) {
    int idx = blockIdx.x * blockDim.x + threadIdx.x;   // over N*H/4
    int n = idx / (Hdim / 4);
    int c = idx % (Hdim / 4);
    float w0 = g_w[2*n],   w1 = g_w[2*n+1];
    int   p0 = g_pos[2*n], p1 = g_pos[2*n+1];
    float4 a = ((const float4*)(g_og + (size_t)p0 * Hdim))[c];
    float4 b = ((const float4*)(g_og + (size_t)p1 * Hdim))[c];
    float4 r;
    r.x = w0 * a.x + w1 * b.x;
    r.y = w0 * a.y + w1 * b.y;
    r.z = w0 * a.z + w1 * b.z;
    r.w = w0 * a.w + w1 * b.w;
    ((float4*)out)[idx] = r;
}

// ---------------- fp16 mma.sync grouped GEMM ---------------------------------
// C[m,nc] = sum_k A[m,k] * W[e][nc,k], both operands fp16 K-contiguous ("row.col").
// CTA tile 128x128x64; 8 warps, warp tile 64x32 (4x4 m16n8k16). 4-stage cp.async.
// SMEM row = 128B = 64 halfs (one K-chunk); XOR-8 swizzle on 16B segments.
#define STAGE_BYTES 32768           // A 16KB + B 16KB
#define NSTAGE 4
#define SMEM_TOTAL (NSTAGE * STAGE_BYTES)

// MODE 0: C float (no act). MODE 1: silu + C half.
template <int MODE>
__global__ __launch_bounds__(256) void moe_gemm_f16(
    const __half* __restrict__ Ab, const __half* __restrict__ Wb,
    void* __restrict__ Cb, int Kdim, int Ncols)
{
    int e  = blockIdx.z;
    int Me = g_counts[e];
    int m0 = blockIdx.y * 128;
    if (m0 >= Me) return;
    int n0  = blockIdx.x * 128;
    int off = g_off[e];

    extern __shared__ char smem[];
    uint32_t sb = smem_u32(smem);
    int tid = threadIdx.x, wid = tid >> 5, lane = tid & 31;

    const __half* A = Ab + (size_t)off * Kdim;
    const __half* W = Wb + (size_t)e * Ncols * Kdim;

    // ---- staging: threads 0-127 load A rows, 128-255 load B rows ------------
    int  srow = tid & 127;
    bool isB  = tid >= 128;
    const __half* gsrc = isB ? (W + (size_t)(n0 + srow) * Kdim)
                             : (A + (size_t)min(m0 + srow, NSLOT - 1 - off) * Kdim);
    uint32_t sdst = sb + (isB ? 16384u : 0u) + (uint32_t)srow * 128u;
    uint32_t sx   = (uint32_t)(srow & 7);

    // ---- ldmatrix address bases ---------------------------------------------
    int mw = wid & 1, nw = wid >> 1;           // warp grid 2(m) x 4(n)
    int mA0 = mw * 64, nB0 = nw * 32;

    // A: matrix q = lane>>3: (q&1)*8 row-block, q>>1 k-half(16B)
    int rA = mA0 + ((lane >> 3) & 1) * 8 + (lane & 7);
    uint32_t jhA = (uint32_t)(lane >> 4);
    uint32_t xA  = (uint32_t)(rA & 7);
    uint32_t baseA[4];
    #pragma unroll
    for (int mt = 0; mt < 4; mt++) baseA[mt] = sb + (uint32_t)(rA + mt * 16) * 128u;

    // B: matrix q: q&1 = k-half, q>>1 = n+8 block; pair p covers ntiles 2p,2p+1
    uint32_t jhB = (uint32_t)((lane >> 3) & 1);
    uint32_t baseB[2], xB[2];
    #pragma unroll
    for (int p = 0; p < 2; p++) {
        int rB = nB0 + p * 16 + (lane >> 4) * 8 + (lane & 7);
        baseB[p] = sb + 16384u + (uint32_t)rB * 128u;
        xB[p]    = (uint32_t)(rB & 7);
    }

    float acc[4][4][4];
    #pragma unroll
    for (int i = 0; i < 4; i++)
        #pragma unroll
        for (int j = 0; j < 4; j++)
            #pragma unroll
            for (int q = 0; q < 4; q++) acc[i][j][q] = 0.f;

    int niter = Kdim >> 6;   // K-chunk 64

    // ---- prologue: stages 0..2 ----------------------------------------------
    #pragma unroll
    for (int s = 0; s < NSTAGE - 1; s++) {
        uint32_t d = sdst + (uint32_t)s * STAGE_BYTES;
        const __half* g = gsrc + s * 64;
        #pragma unroll
        for (int j = 0; j < 8; j++) cp16(d + (((uint32_t)j ^ sx) << 4), g + j * 8);
        asm volatile("cp.async.commit_group;");
    }

    for (int it = 0; it < niter; ++it) {
        asm volatile("cp.async.wait_group 2;");
        __syncthreads();

        uint32_t soff = (uint32_t)(it & (NSTAGE - 1)) * STAGE_BYTES;

        #pragma unroll
        for (int ks = 0; ks < 4; ks++) {   // 4 x k16 = K64
            uint32_t a[4][4];
            #pragma unroll
            for (int mt = 0; mt < 4; mt++) {
                uint32_t ad = baseA[mt] + soff + ((((uint32_t)(ks << 1) + jhA) ^ xA) << 4);
                ldsm_x4(ad, a[mt][0], a[mt][1], a[mt][2], a[mt][3]);
            }
            #pragma unroll
            for (int p = 0; p < 2; p++) {
                uint32_t b0, b1, b2, b3;
                uint32_t bd = baseB[p] + soff + ((((uint32_t)(ks << 1) + jhB) ^ xB[p]) << 4);
                ldsm_x4(bd, b0, b1, b2, b3);
                #pragma unroll
                for (int mt = 0; mt < 4; mt++) {
                    mma_f16(acc[mt][2 * p + 0], a[mt], b0, b1);
                    mma_f16(acc[mt][2 * p + 1], a[mt], b2, b3);
                }
            }
        }

        int nx = it + NSTAGE - 1;
        if (nx < niter) {
            uint32_t d = sdst + (uint32_t)(nx & (NSTAGE - 1)) * STAGE_BYTES;
            const __half* g = gsrc + nx * 64;
            #pragma unroll
            for (int j = 0; j < 8; j++) cp16(d + (((uint32_t)j ^ sx) << 4), g + j * 8);
        }
        asm volatile("cp.async.commit_group;");
    }

    // ---- epilogue ------------------------------------------------------------
    #pragma unroll
    for (int mt = 0; mt < 4; mt++) {
        int ml0 = mA0 + mt * 16 + (lane >> 2);
        int ml1 = ml0 + 8;
        bool w0 = (m0 + ml0) < Me;
        bool w1 = (m0 + ml1) < Me;
        #pragma unroll
        for (int nt = 0; nt < 4; nt++) {
            int col = nB0 + nt * 8 + (lane & 3) * 2;
            float v0 = acc[mt][nt][0], v1 = acc[mt][nt][1];
            float v2 = acc[mt][nt][2], v3 = acc[mt][nt][3];
            if (MODE == 1) {
                v0 = v0 / (1.f + __expf(-v0));
                v1 = v1 / (1.f + __expf(-v1));
                v2 = v2 / (1.f + __expf(-v2));
                v3 = v3 / (1.f + __expf(-v3));
                __half* C = (__half*)Cb + (size_t)off * Ncols;
                if (w0) *(__half2*)(C + (size_t)(m0 + ml0) * Ncols + n0 + col)
                            = __floats2half2_rn(v0, v1);
                if (w1) *(__half2*)(C + (size_t)(m0 + ml1) * Ncols + n0 + col)
                            = __floats2half2_rn(v2, v3);
            } else {
                float* C = (float*)Cb + (size_t)off * Ncols;
                if (w0) *(float2*)(C + (size_t)(m0 + ml0) * Ncols + n0 + col)
                            = make_float2(v0, v1);
                if (w1) *(float2*)(C + (size_t)(m0 + ml1) * Ncols + n0 + col)
                            = make_float2(v2, v3);
            }
        }
    }
}

// ---------------- launch ------------------------------------------------------
extern "C" void kernel_launch(void* const* d_in, const int* in_sizes, int n_in,
                              void* d_out, int out_size) {
    const float* x  = (const float*)d_in[0];
    const float* Wg = (const float*)d_in[1];
    const float* W1 = (const float*)d_in[2];
    const float* W2 = (const float*)d_in[3];
    float* out = (float*)d_out;

    __half *xh = nullptr, *hidh = nullptr, *w1h = nullptr, *w2h = nullptr;
    float  *og = nullptr;
    cudaGetSymbolAddress((void**)&xh,   g_xh);
    cudaGetSymbolAddress((void**)&hidh, g_hidh);
    cudaGetSymbolAddress((void**)&og,   g_og);
    cudaGetSymbolAddress((void**)&w1h,  g_w1h);
    cudaGetSymbolAddress((void**)&w2h,  g_w2h);

    static bool attr_set = false;
    if (!attr_set) {
        cudaFuncSetAttribute(moe_gemm_f16<0>, cudaFuncAttributeMaxDynamicSharedMemorySize,
                             SMEM_TOTAL);
        cudaFuncSetAttribute(moe_gemm_f16<1>, cudaFuncAttributeMaxDynamicSharedMemorySize,
                             SMEM_TOTAL);
        attr_set = true;
    }

    zero_counts_kernel<<<1, 32>>>();
    gate_kernel<<<Ntok, 256>>>(x, Wg);
    scan_kernel<<<1, 32>>>();
    gather_kernel<<<NSLOT, 256>>>(x);
    f2h_kernel<<<(W1ELEMS / 8 + 255) / 256, 256>>>(W1, w1h, W1ELEMS / 8);
    f2h_kernel<<<(W2ELEMS / 8 + 255) / 256, 256>>>(W2, w2h, W2ELEMS / 8);

    // GEMM1: hid = silu(xh @ W1[e]^T)   K=H=1024, Ncols=I=2048
    {
        dim3 grid(Idim / 128, NSLOT / 128, Edim);
        moe_gemm_f16<1><<<grid, 256, SMEM_TOTAL>>>(xh, w1h, hidh, Hdim, Idim);
    }
    // GEMM2: og = hidh @ W2[e]^T        K=I=2048, Ncols=H=1024
    {
        dim3 grid(Hdim / 128, NSLOT / 128, Edim);
        moe_gemm_f16<0><<<grid, 256, SMEM_TOTAL>>>(hidh, w2h, og, Idim, Hdim);
    }
    combine_kernel<<<(Ntok * Hdim / 4) / 256, 256>>>(out);
}

// round 5
// speedup vs baseline: 4.7732x; 1.2647x over previous
#include <cuda_runtime.h>
#include <cuda_fp16.h>
#include <math.h>
#include <stdint.h>

// Problem constants (fixed by the reference)
#define Hdim 1024
#define Idim 2048
#define Edim 8
#define Ntok 8192            // B*T
#define KSEL 2
#define NSLOT (Ntok * KSEL)  // 16384
#define W1ELEMS (Edim * Idim * Hdim)
#define W2ELEMS (Edim * Hdim * Idim)

// ---------------- device scratch ---------------------------------------------
__device__ __half g_xh  [(size_t)NSLOT * Hdim];  // gathered activations (fp16)
__device__ __half g_hidh[(size_t)NSLOT * Idim];  // fc1 out after silu (fp16)
__device__ float  g_og  [(size_t)NSLOT * Hdim];  // fc2 out (fp32)
__device__ __half g_w1h [W1ELEMS];
__device__ __half g_w2h [W2ELEMS];
__device__ int    g_counts[Edim];
__device__ int    g_off[Edim];
__device__ int    g_expert[NSLOT];
__device__ int    g_rank[NSLOT];
__device__ float  g_w[NSLOT];
__device__ int    g_pos[NSLOT];

// ---------------- helpers -----------------------------------------------------
__device__ __forceinline__ uint32_t smem_u32(const void* p) {
    uint32_t a;
    asm("{ .reg .u64 t; cvta.to.shared.u64 t, %1; cvt.u32.u64 %0, t; }" : "=r"(a) : "l"(p));
    return a;
}

__device__ __forceinline__ void cp16(uint32_t dst, const void* src) {
    asm volatile("cp.async.cg.shared.global [%0], [%1], 16;" :: "r"(dst), "l"(src));
}

__device__ __forceinline__ void ldsm_x4(uint32_t addr, uint32_t& r0, uint32_t& r1,
                                        uint32_t& r2, uint32_t& r3) {
    asm volatile("ldmatrix.sync.aligned.m8n8.x4.shared.b16 {%0,%1,%2,%3}, [%4];"
                 : "=r"(r0), "=r"(r1), "=r"(r2), "=r"(r3) : "r"(addr));
}

__device__ __forceinline__ void mma_f16(float* d, const uint32_t* a, uint32_t b0, uint32_t b1) {
    asm volatile(
        "mma.sync.aligned.m16n8k16.row.col.f32.f16.f16.f32 "
        "{%0,%1,%2,%3}, {%4,%5,%6,%7}, {%8,%9}, {%0,%1,%2,%3};"
        : "+f"(d[0]), "+f"(d[1]), "+f"(d[2]), "+f"(d[3])
        : "r"(a[0]), "r"(a[1]), "r"(a[2]), "r"(a[3]), "r"(b0), "r"(b1));
}

// ---------------- ancillary kernels ------------------------------------------
__global__ void zero_counts_kernel() {
    if (threadIdx.x < Edim) g_counts[threadIdx.x] = 0;
}

__global__ __launch_bounds__(256) void gate_kernel(const float* __restrict__ x,
                                                   const float* __restrict__ Wg) {
    int n    = blockIdx.x;
    int warp = threadIdx.x >> 5;
    int lane = threadIdx.x & 31;

    const float* xr = x  + (size_t)n * Hdim;
    const float* wr = Wg + (size_t)warp * Hdim;
    float s = 0.f;
    #pragma unroll 8
    for (int h = lane; h < Hdim; h += 32) s += xr[h] * wr[h];
    #pragma unroll
    for (int o = 16; o; o >>= 1) s += __shfl_xor_sync(0xFFFFFFFFu, s, o);

    __shared__ float logits[Edim];
    if (lane == 0) logits[warp] = s;
    __syncthreads();

    if (threadIdx.x == 0) {
        float m = logits[0];
        #pragma unroll
        for (int e = 1; e < Edim; e++) m = fmaxf(m, logits[e]);
        float p[Edim]; float den = 0.f;
        #pragma unroll
        for (int e = 0; e < Edim; e++) { p[e] = expf(logits[e] - m); den += p[e]; }
        int i0 = 0;
        #pragma unroll
        for (int e = 1; e < Edim; e++) if (p[e] > p[i0]) i0 = e;
        int i1 = (i0 == 0) ? 1 : 0;
        #pragma unroll
        for (int e = 0; e < Edim; e++) if (e != i0 && p[e] > p[i1]) i1 = e;
        float inv = 1.f / den;
        int r0 = atomicAdd(&g_counts[i0], 1);
        int r1 = atomicAdd(&g_counts[i1], 1);
        g_expert[2*n]   = i0; g_rank[2*n]   = r0; g_w[2*n]   = p[i0] * inv;
        g_expert[2*n+1] = i1; g_rank[2*n+1] = r1; g_w[2*n+1] = p[i1] * inv;
    }
}

__global__ void scan_kernel() {
    if (threadIdx.x == 0) {
        int a = 0;
        #pragma unroll
        for (int e = 0; e < Edim; e++) { g_off[e] = a; a += g_counts[e]; }
    }
}

__global__ __launch_bounds__(256) void gather_kernel(const float* __restrict__ x) {
    int slot = blockIdx.x;
    int e    = g_expert[slot];
    int pos  = g_off[e] + g_rank[slot];
    if (threadIdx.x == 0) g_pos[slot] = pos;
    int n = slot >> 1;
    const float4* src = (const float4*)(x + (size_t)n * Hdim);
    __half2*      dst = (__half2*)(g_xh + (size_t)pos * Hdim);
    for (int i = threadIdx.x; i < Hdim / 4; i += blockDim.x) {
        float4 v = src[i];
        dst[2*i]   = __floats2half2_rn(v.x, v.y);
        dst[2*i+1] = __floats2half2_rn(v.z, v.w);
    }
}

// float -> half weight conversion, 8 elems per thread
__global__ __launch_bounds__(256) void f2h_kernel(const float* __restrict__ s,
                                                  __half* __restrict__ d, int n8) {
    int i = blockIdx.x * blockDim.x + threadIdx.x;
    if (i >= n8) return;
    float4 v0 = ((const float4*)s)[2*i];
    float4 v1 = ((const float4*)s)[2*i+1];
    __half2 h[4];
    h[0] = __floats2half2_rn(v0.x, v0.y);
    h[1] = __floats2half2_rn(v0.z, v0.w);
    h[2] = __floats2half2_rn(v1.x, v1.y);
    h[3] = __floats2half2_rn(v1.z, v1.w);
    ((uint4*)d)[i] = *(uint4*)h;
}

__global__ __launch_bounds__(256) void combine_kernel(float* __restrict__ out) {
    int idx = blockIdx.x * blockDim.x + threadIdx.x;   // over N*H/4
    int n = idx / (Hdim / 4);
    int c = idx % (Hdim / 4);
    float w0 = g_w[2*n],   w1 = g_w[2*n+1];
    int   p0 = g_pos[2*n], p1 = g_pos[2*n+1];
    float4 a = ((const float4*)(g_og + (size_t)p0 * Hdim))[c];
    float4 b = ((const float4*)(g_og + (size_t)p1 * Hdim))[c];
    float4 r;
    r.x = w0 * a.x + w1 * b.x;
    r.y = w0 * a.y + w1 * b.y;
    r.z = w0 * a.z + w1 * b.z;
    r.w = w0 * a.w + w1 * b.w;
    ((float4*)out)[idx] = r;
}

// ---------------- fp16 mma.sync grouped GEMM ---------------------------------
// C[m,nc] = sum_k A[m,k] * W[e][nc,k], both operands fp16 K-contiguous ("row.col").
// CTA tile 128x128x64; 8 warps, warp tile 64x32 (4x4 m16n8k16).
// 3-stage cp.async pipeline (96KB) -> 2 CTAs/SM for latency hiding.
#define STAGE_BYTES 32768           // A 16KB + B 16KB
#define NSTAGE 3
#define SMEM_TOTAL (NSTAGE * STAGE_BYTES)

// MODE 0: C float (no act). MODE 1: silu + C half.
template <int MODE>
__global__ __launch_bounds__(256, 2) void moe_gemm_f16(
    const __half* __restrict__ Ab, const __half* __restrict__ Wb,
    void* __restrict__ Cb, int Kdim, int Ncols)
{
    int e  = blockIdx.z;
    int Me = g_counts[e];
    int m0 = blockIdx.y * 128;
    if (m0 >= Me) return;
    int n0  = blockIdx.x * 128;
    int off = g_off[e];

    extern __shared__ char smem[];
    uint32_t sb = smem_u32(smem);
    int tid = threadIdx.x, wid = tid >> 5, lane = tid & 31;

    const __half* A = Ab + (size_t)off * Kdim;
    const __half* W = Wb + (size_t)e * Ncols * Kdim;

    // ---- staging: threads 0-127 load A rows, 128-255 load B rows ------------
    int  srow = tid & 127;
    bool isB  = tid >= 128;
    const __half* gsrc = isB ? (W + (size_t)(n0 + srow) * Kdim)
                             : (A + (size_t)min(m0 + srow, NSLOT - 1 - off) * Kdim);
    uint32_t sdst = sb + (isB ? 16384u : 0u) + (uint32_t)srow * 128u;
    uint32_t sx   = (uint32_t)(srow & 7);

    // ---- ldmatrix address bases ---------------------------------------------
    int mw = wid & 1, nw = wid >> 1;           // warp grid 2(m) x 4(n)
    int mA0 = mw * 64, nB0 = nw * 32;

    // A: matrix q = lane>>3: (q&1)*8 row-block, q>>1 k-half(16B)
    int rA = mA0 + ((lane >> 3) & 1) * 8 + (lane & 7);
    uint32_t jhA = (uint32_t)(lane >> 4);
    uint32_t xA  = (uint32_t)(rA & 7);
    uint32_t baseA[4];
    #pragma unroll
    for (int mt = 0; mt < 4; mt++) baseA[mt] = sb + (uint32_t)(rA + mt * 16) * 128u;

    // B: matrix q: q&1 = k-half, q>>1 = n+8 block; pair p covers ntiles 2p,2p+1
    uint32_t jhB = (uint32_t)((lane >> 3) & 1);
    uint32_t baseB[2], xB[2];
    #pragma unroll
    for (int p = 0; p < 2; p++) {
        int rB = nB0 + p * 16 + (lane >> 4) * 8 + (lane & 7);
        baseB[p] = sb + 16384u + (uint32_t)rB * 128u;
        xB[p]    = (uint32_t)(rB & 7);
    }

    float acc[4][4][4];
    #pragma unroll
    for (int i = 0; i < 4; i++)
        #pragma unroll
        for (int j = 0; j < 4; j++)
            #pragma unroll
            for (int q = 0; q < 4; q++) acc[i][j][q] = 0.f;

    int niter = Kdim >> 6;   // K-chunk 64

    // ---- prologue: stages 0,1 -----------------------------------------------
    #pragma unroll
    for (int s = 0; s < NSTAGE - 1; s++) {
        uint32_t d = sdst + (uint32_t)s * STAGE_BYTES;
        const __half* g = gsrc + s * 64;
        #pragma unroll
        for (int j = 0; j < 8; j++) cp16(d + (((uint32_t)j ^ sx) << 4), g + j * 8);
        asm volatile("cp.async.commit_group;");
    }

    int s_idx = 0;               // compute slot
    int l_idx = NSTAGE - 1;      // next load slot
    for (int it = 0; it < niter; ++it) {
        asm volatile("cp.async.wait_group 1;");
        __syncthreads();

        uint32_t soff = (uint32_t)s_idx * STAGE_BYTES;

        #pragma unroll
        for (int ks = 0; ks < 4; ks++) {   // 4 x k16 = K64
            uint32_t a[4][4];
            #pragma unroll
            for (int mt = 0; mt < 4; mt++) {
                uint32_t ad = baseA[mt] + soff + ((((uint32_t)(ks << 1) + jhA) ^ xA) << 4);
                ldsm_x4(ad, a[mt][0], a[mt][1], a[mt][2], a[mt][3]);
            }
            #pragma unroll
            for (int p = 0; p < 2; p++) {
                uint32_t b0, b1, b2, b3;
                uint32_t bd = baseB[p] + soff + ((((uint32_t)(ks << 1) + jhB) ^ xB[p]) << 4);
                ldsm_x4(bd, b0, b1, b2, b3);
                #pragma unroll
                for (int mt = 0; mt < 4; mt++) {
                    mma_f16(acc[mt][2 * p + 0], a[mt], b0, b1);
                    mma_f16(acc[mt][2 * p + 1], a[mt], b2, b3);
                }
            }
        }

        int nx = it + NSTAGE - 1;
        if (nx < niter) {
            uint32_t d = sdst + (uint32_t)l_idx * STAGE_BYTES;
            const __half* g = gsrc + nx * 64;
            #pragma unroll
            for (int j = 0; j < 8; j++) cp16(d + (((uint32_t)j ^ sx) << 4), g + j * 8);
        }
        asm volatile("cp.async.commit_group;");

        s_idx = (s_idx == NSTAGE - 1) ? 0 : s_idx + 1;
        l_idx = (l_idx == NSTAGE - 1) ? 0 : l_idx + 1;
    }

    // ---- epilogue ------------------------------------------------------------
    #pragma unroll
    for (int mt = 0; mt < 4; mt++) {
        int ml0 = mA0 + mt * 16 + (lane >> 2);
        int ml1 = ml0 + 8;
        bool w0 = (m0 + ml0) < Me;
        bool w1 = (m0 + ml1) < Me;
        #pragma unroll
        for (int nt = 0; nt < 4; nt++) {
            int col = nB0 + nt * 8 + (lane & 3) * 2;
            float v0 = acc[mt][nt][0], v1 = acc[mt][nt][1];
            float v2 = acc[mt][nt][2], v3 = acc[mt][nt][3];
            if (MODE == 1) {
                v0 = v0 / (1.f + __expf(-v0));
                v1 = v1 / (1.f + __expf(-v1));
                v2 = v2 / (1.f + __expf(-v2));
                v3 = v3 / (1.f + __expf(-v3));
                __half* C = (__half*)Cb + (size_t)off * Ncols;
                if (w0) *(__half2*)(C + (size_t)(m0 + ml0) * Ncols + n0 + col)
                            = __floats2half2_rn(v0, v1);
                if (w1) *(__half2*)(C + (size_t)(m0 + ml1) * Ncols + n0 + col)
                            = __floats2half2_rn(v2, v3);
            } else {
                float* C = (float*)Cb + (size_t)off * Ncols;
                if (w0) *(float2*)(C + (size_t)(m0 + ml0) * Ncols + n0 + col)
                            = make_float2(v0, v1);
                if (w1) *(float2*)(C + (size_t)(m0 + ml1) * Ncols + n0 + col)
                            = make_float2(v2, v3);
            }
        }
    }
}

// ---------------- launch ------------------------------------------------------
extern "C" void kernel_launch(void* const* d_in, const int* in_sizes, int n_in,
                              void* d_out, int out_size) {
    const float* x  = (const float*)d_in[0];
    const float* Wg = (const float*)d_in[1];
    const float* W1 = (const float*)d_in[2];
    const float* W2 = (const float*)d_in[3];
    float* out = (float*)d_out;

    __half *xh = nullptr, *hidh = nullptr, *w1h = nullptr, *w2h = nullptr;
    float  *og = nullptr;
    cudaGetSymbolAddress((void**)&xh,   g_xh);
    cudaGetSymbolAddress((void**)&hidh, g_hidh);
    cudaGetSymbolAddress((void**)&og,   g_og);
    cudaGetSymbolAddress((void**)&w1h,  g_w1h);
    cudaGetSymbolAddress((void**)&w2h,  g_w2h);

    static bool attr_set = false;
    if (!attr_set) {
        cudaFuncSetAttribute(moe_gemm_f16<0>, cudaFuncAttributeMaxDynamicSharedMemorySize,
                             SMEM_TOTAL);
        cudaFuncSetAttribute(moe_gemm_f16<1>, cudaFuncAttributeMaxDynamicSharedMemorySize,
                             SMEM_TOTAL);
        attr_set = true;
    }

    zero_counts_kernel<<<1, 32>>>();
    gate_kernel<<<Ntok, 256>>>(x, Wg);
    scan_kernel<<<1, 32>>>();
    gather_kernel<<<NSLOT, 256>>>(x);
    f2h_kernel<<<(W1ELEMS / 8 + 255) / 256, 256>>>(W1, w1h, W1ELEMS / 8);
    f2h_kernel<<<(W2ELEMS / 8 + 255) / 256, 256>>>(W2, w2h, W2ELEMS / 8);

    // GEMM1: hid = silu(xh @ W1[e]^T)   K=H=1024, Ncols=I=2048
    {
        dim3 grid(Idim / 128, NSLOT / 128, Edim);
        moe_gemm_f16<1><<<grid, 256, SMEM_TOTAL>>>(xh, w1h, hidh, Hdim, Idim);
    }
    // GEMM2: og = hidh @ W2[e]^T        K=I=2048, Ncols=H=1024
    {
        dim3 grid(Hdim / 128, NSLOT / 128, Edim);
        moe_gemm_f16<0><<<grid, 256, SMEM_TOTAL>>>(hidh, w2h, og, Idim, Hdim);
    }
    combine_kernel<<<(Ntok * Hdim / 4) / 256, 256>>>(out);
}

// round 6
// speedup vs baseline: 4.8415x; 1.0143x over previous
#include <cuda_runtime.h>
#include <cuda_fp16.h>
#include <math.h>
#include <stdint.h>

// Problem constants (fixed by the reference)
#define Hdim 1024
#define Idim 2048
#define Edim 8
#define Ntok 8192            // B*T
#define KSEL 2
#define NSLOT (Ntok * KSEL)  // 16384
#define W1ELEMS (Edim * Idim * Hdim)
#define W2ELEMS (Edim * Hdim * Idim)

// ---------------- device scratch ---------------------------------------------
__device__ __half g_xh  [(size_t)NSLOT * Hdim];  // gathered activations (fp16)
__device__ __half g_hidh[(size_t)NSLOT * Idim];  // fc1 out after silu (fp16)
__device__ __half g_ogh [(size_t)NSLOT * Hdim];  // fc2 out (fp16)
__device__ __half g_w1h [W1ELEMS];
__device__ __half g_w2h [W2ELEMS];
__device__ int    g_counts[Edim];
__device__ int    g_off[Edim];
__device__ int    g_expert[NSLOT];
__device__ int    g_rank[NSLOT];
__device__ float  g_w[NSLOT];
__device__ int    g_pos[NSLOT];

// ---------------- helpers -----------------------------------------------------
__device__ __forceinline__ uint32_t smem_u32(const void* p) {
    uint32_t a;
    asm("{ .reg .u64 t; cvta.to.shared.u64 t, %1; cvt.u32.u64 %0, t; }" : "=r"(a) : "l"(p));
    return a;
}

__device__ __forceinline__ void cp16(uint32_t dst, const void* src) {
    asm volatile("cp.async.cg.shared.global [%0], [%1], 16;" :: "r"(dst), "l"(src));
}

__device__ __forceinline__ void ldsm_x4(uint32_t addr, uint32_t& r0, uint32_t& r1,
                                        uint32_t& r2, uint32_t& r3) {
    asm volatile("ldmatrix.sync.aligned.m8n8.x4.shared.b16 {%0,%1,%2,%3}, [%4];"
                 : "=r"(r0), "=r"(r1), "=r"(r2), "=r"(r3) : "r"(addr));
}

__device__ __forceinline__ void mma_f16(float* d, const uint32_t* a, uint32_t b0, uint32_t b1) {
    asm volatile(
        "mma.sync.aligned.m16n8k16.row.col.f32.f16.f16.f32 "
        "{%0,%1,%2,%3}, {%4,%5,%6,%7}, {%8,%9}, {%0,%1,%2,%3};"
        : "+f"(d[0]), "+f"(d[1]), "+f"(d[2]), "+f"(d[3])
        : "r"(a[0]), "r"(a[1]), "r"(a[2]), "r"(a[3]), "r"(b0), "r"(b1));
}

// ---------------- ancillary kernels ------------------------------------------
__global__ void zero_counts_kernel() {
    if (threadIdx.x < Edim) g_counts[threadIdx.x] = 0;
}

__global__ __launch_bounds__(256) void gate_kernel(const float* __restrict__ x,
                                                   const float* __restrict__ Wg) {
    int n    = blockIdx.x;
    int warp = threadIdx.x >> 5;
    int lane = threadIdx.x & 31;

    const float* xr = x  + (size_t)n * Hdim;
    const float* wr = Wg + (size_t)warp * Hdim;
    float s = 0.f;
    #pragma unroll 8
    for (int h = lane; h < Hdim; h += 32) s += xr[h] * wr[h];
    #pragma unroll
    for (int o = 16; o; o >>= 1) s += __shfl_xor_sync(0xFFFFFFFFu, s, o);

    __shared__ float logits[Edim];
    if (lane == 0) logits[warp] = s;
    __syncthreads();

    if (threadIdx.x == 0) {
        float m = logits[0];
        #pragma unroll
        for (int e = 1; e < Edim; e++) m = fmaxf(m, logits[e]);
        float p[Edim]; float den = 0.f;
        #pragma unroll
        for (int e = 0; e < Edim; e++) { p[e] = expf(logits[e] - m); den += p[e]; }
        int i0 = 0;
        #pragma unroll
        for (int e = 1; e < Edim; e++) if (p[e] > p[i0]) i0 = e;
        int i1 = (i0 == 0) ? 1 : 0;
        #pragma unroll
        for (int e = 0; e < Edim; e++) if (e != i0 && p[e] > p[i1]) i1 = e;
        float inv = 1.f / den;
        int r0 = atomicAdd(&g_counts[i0], 1);
        int r1 = atomicAdd(&g_counts[i1], 1);
        g_expert[2*n]   = i0; g_rank[2*n]   = r0; g_w[2*n]   = p[i0] * inv;
        g_expert[2*n+1] = i1; g_rank[2*n+1] = r1; g_w[2*n+1] = p[i1] * inv;
    }
}

__global__ void scan_kernel() {
    if (threadIdx.x == 0) {
        int a = 0;
        #pragma unroll
        for (int e = 0; e < Edim; e++) { g_off[e] = a; a += g_counts[e]; }
    }
}

__global__ __launch_bounds__(256) void gather_kernel(const float* __restrict__ x) {
    int slot = blockIdx.x;
    int e    = g_expert[slot];
    int pos  = g_off[e] + g_rank[slot];
    if (threadIdx.x == 0) g_pos[slot] = pos;
    int n = slot >> 1;
    const float4* src = (const float4*)(x + (size_t)n * Hdim);
    __half2*      dst = (__half2*)(g_xh + (size_t)pos * Hdim);
    for (int i = threadIdx.x; i < Hdim / 4; i += blockDim.x) {
        float4 v = src[i];
        dst[2*i]   = __floats2half2_rn(v.x, v.y);
        dst[2*i+1] = __floats2half2_rn(v.z, v.w);
    }
}

// float -> half weight conversion, 8 elems per thread
__global__ __launch_bounds__(256) void f2h_kernel(const float* __restrict__ s,
                                                  __half* __restrict__ d, int n8) {
    int i = blockIdx.x * blockDim.x + threadIdx.x;
    if (i >= n8) return;
    float4 v0 = ((const float4*)s)[2*i];
    float4 v1 = ((const float4*)s)[2*i+1];
    __half2 h[4];
    h[0] = __floats2half2_rn(v0.x, v0.y);
    h[1] = __floats2half2_rn(v0.z, v0.w);
    h[2] = __floats2half2_rn(v1.x, v1.y);
    h[3] = __floats2half2_rn(v1.z, v1.w);
    ((uint4*)d)[i] = *(uint4*)h;
}

__global__ __launch_bounds__(256) void combine_kernel(float* __restrict__ out) {
    int idx = blockIdx.x * blockDim.x + threadIdx.x;   // over N*H/4
    int n = idx / (Hdim / 4);
    int c = idx % (Hdim / 4);
    float w0 = g_w[2*n],   w1 = g_w[2*n+1];
    int   p0 = g_pos[2*n], p1 = g_pos[2*n+1];
    __half2 a0 = ((const __half2*)(g_ogh + (size_t)p0 * Hdim))[2*c];
    __half2 a1 = ((const __half2*)(g_ogh + (size_t)p0 * Hdim))[2*c+1];
    __half2 b0 = ((const __half2*)(g_ogh + (size_t)p1 * Hdim))[2*c];
    __half2 b1 = ((const __half2*)(g_ogh + (size_t)p1 * Hdim))[2*c+1];
    float2 fa0 = __half22float2(a0), fa1 = __half22float2(a1);
    float2 fb0 = __half22float2(b0), fb1 = __half22float2(b1);
    float4 r;
    r.x = w0 * fa0.x + w1 * fb0.x;
    r.y = w0 * fa0.y + w1 * fb0.y;
    r.z = w0 * fa1.x + w1 * fb1.x;
    r.w = w0 * fa1.y + w1 * fb1.y;
    ((float4*)out)[idx] = r;
}

// ---------------- fp16 mma.sync grouped GEMM ---------------------------------
// C[m,nc] = sum_k A[m,k] * W[e][nc,k], fp16 K-contiguous both sides ("row.col").
// CTA tile 128x256x64; 8 warps as 2(m)x4(n), warp tile 64x64 (4x8 m16n8k16).
// 4-stage cp.async pipeline (192KB SMEM, 1 CTA/SM); depth-2 prefetch.
// Stage layout: rows 0..127 = A (16KB), rows 128..383 = B (32KB); 128B rows,
// XOR-8 swizzle on 16B segments within each row group of 8.
#define STAGE_BYTES 49152
#define NSTAGE 4
#define SMEM_TOTAL (NSTAGE * STAGE_BYTES)

// MODE 0: plain C half. MODE 1: silu + C half.
template <int MODE>
__global__ __launch_bounds__(256, 1) void moe_gemm_f16(
    const __half* __restrict__ Ab, const __half* __restrict__ Wb,
    __half* __restrict__ Cb, int Kdim, int Ncols)
{
    int e  = blockIdx.z;
    int Me = g_counts[e];
    int m0 = blockIdx.y * 128;
    if (m0 >= Me) return;
    int n0  = blockIdx.x * 256;
    int off = g_off[e];

    extern __shared__ char smem[];
    uint32_t sb = smem_u32(smem);
    int tid = threadIdx.x, wid = tid >> 5, lane = tid & 31;

    const __half* A = Ab + (size_t)off * Kdim;
    const __half* W = Wb + (size_t)e * Ncols * Kdim;

    // ---- staging: row index ri in [0,384): ri<128 -> A row ri; else B row ri-128
    // thread t loads ri1 = t; threads t<128 also load ri2 = t+256.
    int ri1 = tid;
    const __half* gs1 = (ri1 < 128)
        ? (A + (size_t)min(m0 + ri1, NSLOT - 1 - off) * Kdim)
        : (W + (size_t)(n0 + ri1 - 128) * Kdim);
    uint32_t d1 = sb + (uint32_t)ri1 * 128u;
    uint32_t x1 = (uint32_t)(ri1 & 7);

    int ri2 = tid + 256;                       // only for tid < 128 (B rows 128..255)
    const __half* gs2 = W + (size_t)(n0 + (tid & 127) + 128) * Kdim;
    uint32_t d2 = sb + (uint32_t)ri2 * 128u;
    uint32_t x2 = (uint32_t)(ri2 & 7);
    bool two = tid < 128;

    // ---- ldmatrix address bases ---------------------------------------------
    int mw = wid & 1, nw = wid >> 1;           // warp grid 2(m) x 4(n)
    int mA0 = mw * 64, nB0 = nw * 64;

    int rA = mA0 + ((lane >> 3) & 1) * 8 + (lane & 7);
    uint32_t jhA = (uint32_t)(lane >> 4);
    uint32_t xA  = (uint32_t)(rA & 7);
    uint32_t baseA[4];
    #pragma unroll
    for (int mt = 0; mt < 4; mt++) baseA[mt] = sb + (uint32_t)(rA + mt * 16) * 128u;

    uint32_t jhB = (uint32_t)((lane >> 3) & 1);
    uint32_t baseB[4], xB[4];
    #pragma unroll
    for (int p = 0; p < 4; p++) {
        int rB = nB0 + p * 16 + (lane >> 4) * 8 + (lane & 7);
        baseB[p] = sb + 16384u + (uint32_t)rB * 128u;
        xB[p]    = (uint32_t)(rB & 7);
    }

    float acc[4][8][4];
    #pragma unroll
    for (int i = 0; i < 4; i++)
        #pragma unroll
        for (int j = 0; j < 8; j++)
            #pragma unroll
            for (int q = 0; q < 4; q++) acc[i][j][q] = 0.f;

    int niter = Kdim >> 6;   // K-chunk 64

    // ---- prologue: stages 0..2 ----------------------------------------------
    #pragma unroll
    for (int s = 0; s < NSTAGE - 1; s++) {
        uint32_t so = (uint32_t)s * STAGE_BYTES;
        const __half* g1 = gs1 + s * 64;
        #pragma unroll
        for (int j = 0; j < 8; j++) cp16(d1 + so + (((uint32_t)j ^ x1) << 4), g1 + j * 8);
        if (two) {
            const __half* g2 = gs2 + s * 64;
            #pragma unroll
            for (int j = 0; j < 8; j++) cp16(d2 + so + (((uint32_t)j ^ x2) << 4), g2 + j * 8);
        }
        asm volatile("cp.async.commit_group;");
    }

    int s_idx = 0;               // compute slot
    int l_idx = NSTAGE - 1;      // next load slot
    for (int it = 0; it < niter; ++it) {
        asm volatile("cp.async.wait_group 2;");
        __syncthreads();

        uint32_t soff = (uint32_t)s_idx * STAGE_BYTES;

        #pragma unroll
        for (int ks = 0; ks < 4; ks++) {   // 4 x k16 = K64
            uint32_t a[4][4];
            #pragma unroll
            for (int mt = 0; mt < 4; mt++) {
                uint32_t ad = baseA[mt] + soff + ((((uint32_t)(ks << 1) + jhA) ^ xA) << 4);
                ldsm_x4(ad, a[mt][0], a[mt][1], a[mt][2], a[mt][3]);
            }
            #pragma unroll
            for (int p = 0; p < 4; p++) {
                uint32_t b0, b1, b2, b3;
                uint32_t bd = baseB[p] + soff + ((((uint32_t)(ks << 1) + jhB) ^ xB[p]) << 4);
                ldsm_x4(bd, b0, b1, b2, b3);
                #pragma unroll
                for (int mt = 0; mt < 4; mt++) {
                    mma_f16(acc[mt][2 * p + 0], a[mt], b0, b1);
                    mma_f16(acc[mt][2 * p + 1], a[mt], b2, b3);
                }
            }
        }

        int nx = it + NSTAGE - 1;
        if (nx < niter) {
            uint32_t so = (uint32_t)l_idx * STAGE_BYTES;
            const __half* g1 = gs1 + nx * 64;
            #pragma unroll
            for (int j = 0; j < 8; j++) cp16(d1 + so + (((uint32_t)j ^ x1) << 4), g1 + j * 8);
            if (two) {
                const __half* g2 = gs2 + nx * 64;
                #pragma unroll
                for (int j = 0; j < 8; j++) cp16(d2 + so + (((uint32_t)j ^ x2) << 4), g2 + j * 8);
            }
        }
        asm volatile("cp.async.commit_group;");

        s_idx = (s_idx == NSTAGE - 1) ? 0 : s_idx + 1;
        l_idx = (l_idx == NSTAGE - 1) ? 0 : l_idx + 1;
    }

    // ---- epilogue (half output) ---------------------------------------------
    __half* C = Cb + (size_t)off * Ncols;
    #pragma unroll
    for (int mt = 0; mt < 4; mt++) {
        int ml0 = mA0 + mt * 16 + (lane >> 2);
        int ml1 = ml0 + 8;
        bool w0 = (m0 + ml0) < Me;
        bool w1 = (m0 + ml1) < Me;
        __half* c0 = C + (size_t)(m0 + ml0) * Ncols + n0;
        __half* c1 = C + (size_t)(m0 + ml1) * Ncols + n0;
        #pragma unroll
        for (int nt = 0; nt < 8; nt++) {
            int col = nB0 + nt * 8 + (lane & 3) * 2;
            float v0 = acc[mt][nt][0], v1 = acc[mt][nt][1];
            float v2 = acc[mt][nt][2], v3 = acc[mt][nt][3];
            if (MODE == 1) {
                v0 = v0 / (1.f + __expf(-v0));
                v1 = v1 / (1.f + __expf(-v1));
                v2 = v2 / (1.f + __expf(-v2));
                v3 = v3 / (1.f + __expf(-v3));
            }
            if (w0) *(__half2*)(c0 + col) = __floats2half2_rn(v0, v1);
            if (w1) *(__half2*)(c1 + col) = __floats2half2_rn(v2, v3);
        }
    }
}

// ---------------- launch ------------------------------------------------------
extern "C" void kernel_launch(void* const* d_in, const int* in_sizes, int n_in,
                              void* d_out, int out_size) {
    const float* x  = (const float*)d_in[0];
    const float* Wg = (const float*)d_in[1];
    const float* W1 = (const float*)d_in[2];
    const float* W2 = (const float*)d_in[3];
    float* out = (float*)d_out;

    __half *xh = nullptr, *hidh = nullptr, *ogh = nullptr, *w1h = nullptr, *w2h = nullptr;
    cudaGetSymbolAddress((void**)&xh,   g_xh);
    cudaGetSymbolAddress((void**)&hidh, g_hidh);
    cudaGetSymbolAddress((void**)&ogh,  g_ogh);
    cudaGetSymbolAddress((void**)&w1h,  g_w1h);
    cudaGetSymbolAddress((void**)&w2h,  g_w2h);

    static bool attr_set = false;
    if (!attr_set) {
        cudaFuncSetAttribute(moe_gemm_f16<0>, cudaFuncAttributeMaxDynamicSharedMemorySize,
                             SMEM_TOTAL);
        cudaFuncSetAttribute(moe_gemm_f16<1>, cudaFuncAttributeMaxDynamicSharedMemorySize,
                             SMEM_TOTAL);
        attr_set = true;
    }

    zero_counts_kernel<<<1, 32>>>();
    gate_kernel<<<Ntok, 256>>>(x, Wg);
    scan_kernel<<<1, 32>>>();
    gather_kernel<<<NSLOT, 256>>>(x);
    f2h_kernel<<<(W1ELEMS / 8 + 255) / 256, 256>>>(W1, w1h, W1ELEMS / 8);
    f2h_kernel<<<(W2ELEMS / 8 + 255) / 256, 256>>>(W2, w2h, W2ELEMS / 8);

    // GEMM1: hid = silu(xh @ W1[e]^T)   K=H=1024, Ncols=I=2048
    {
        dim3 grid(Idim / 256, NSLOT / 128, Edim);
        moe_gemm_f16<1><<<grid, 256, SMEM_TOTAL>>>(xh, w1h, hidh, Hdim, Idim);
    }
    // GEMM2: og = hidh @ W2[e]^T        K=I=2048, Ncols=H=1024
    {
        dim3 grid(Hdim / 256, NSLOT / 128, Edim);
        moe_gemm_f16<0><<<grid, 256, SMEM_TOTAL>>>(hidh, w2h, ogh, Idim, Hdim);
    }
    combine_kernel<<<(Ntok * Hdim / 4) / 256, 256>>>(out);
}